// round 7
// baseline (speedup 1.0000x reference)
#include <cuda_runtime.h>
#include <math.h>

// Problem constants (fixed shapes from setup_inputs)
#define BB      8
#define KN      768      // K*N = 3*256
#define NPTS    256      // N
#define BETA    192      // int(0.75*N)
#define NCOV    64       // N - BETA
#define C_OUT   128
#define HW_OUT  256
#define C_RES   64
#define HW_RES  512
#define C_FEAT  192
#define REND_ELEMS (BB*C_OUT*NPTS)   // 262144

// Scratch (no allocations allowed)
__device__ float g_unc[BB * KN];
__device__ float g_feat[(size_t)BB * C_FEAT * NPTS];

// ---------------------------------------------------------------------------
// Kernel 1: uncertainty per rand_over point.
// Warp per point: top-2 over 128 channels at each of 4 bilinear corners,
// then bilinear combine exactly mirroring the reference arithmetic order.
// ---------------------------------------------------------------------------
__global__ void unc_kernel(const float* __restrict__ outm,
                           const float* __restrict__ rand_over) {
    int gw   = (blockIdx.x * blockDim.x + threadIdx.x) >> 5;
    int lane = threadIdx.x & 31;
    if (gw >= BB * KN) return;
    int b = gw / KN, p = gw % KN;

    float px = rand_over[(b * KN + p) * 2 + 0];
    float py = rand_over[(b * KN + p) * 2 + 1];
    float gx = px * (float)HW_OUT - 0.5f;
    float gy = py * (float)HW_OUT - 0.5f;
    float x0f = floorf(gx), y0f = floorf(gy);
    float wx = gx - x0f, wy = gy - y0f;
    int x0 = (int)x0f, y0 = (int)y0f;

    const float* base = outm + (size_t)b * C_OUT * HW_OUT * HW_OUT;
    float og0 = 0.0f, og1 = 0.0f;

    #pragma unroll
    for (int cy = 0; cy < 2; cy++) {
        #pragma unroll
        for (int cx = 0; cx < 2; cx++) {
            int yi = y0 + cy, xi = x0 + cx;
            float t1, t2;
            if (xi >= 0 && xi < HW_OUT && yi >= 0 && yi < HW_OUT) {
                t1 = -INFINITY; t2 = -INFINITY;
                const float* pix = base + (size_t)yi * HW_OUT + xi;
                #pragma unroll
                for (int i = 0; i < 4; i++) {
                    float v = __ldg(pix + (size_t)(lane + 32 * i) * (HW_OUT * HW_OUT));
                    if (v > t1) { t2 = t1; t1 = v; }
                    else if (v > t2) { t2 = v; }
                }
                #pragma unroll
                for (int off = 16; off; off >>= 1) {
                    float o1 = __shfl_xor_sync(0xffffffffu, t1, off);
                    float o2 = __shfl_xor_sync(0xffffffffu, t2, off);
                    float n1 = fmaxf(t1, o1);
                    float n2 = fmaxf(fminf(t1, o1), fmaxf(t2, o2));
                    t1 = n1; t2 = n2;
                }
            } else {
                t1 = 0.0f; t2 = 0.0f;   // zero padding
            }
            float fx = cx ? wx : (1.0f - wx);
            float fy = cy ? wy : (1.0f - wy);
            // mirror reference: v * fx * fy, summed in corner order 00,01,10,11
            og0 += (t1 * fx) * fy;
            og1 += (t2 * fx) * fy;
        }
    }
    if (lane == 0) g_unc[b * KN + p] = og1 - og0;   // -(og0 - og1)
}

// ---------------------------------------------------------------------------
// Kernel 2: exact top-BETA selection per batch (matches lax.top_k ordering:
// descending value, ties broken by lower index). Rank-by-comparison O(N^2).
// Writes points (importance then rand_cov) into d_out tail region.
// ---------------------------------------------------------------------------
__global__ void topk_kernel(const float* __restrict__ rand_over,
                            const float* __restrict__ rand_cov,
                            float* __restrict__ pts_out) {
    __shared__ float su[KN];
    int b = blockIdx.x;
    int t = threadIdx.x;       // blockDim.x == KN
    su[t] = g_unc[b * KN + t];
    __syncthreads();
    float v = su[t];
    int rank = 0;
    for (int j = 0; j < KN; j++) {
        float vj = su[j];
        rank += (vj > v) || (vj == v && j < t);
    }
    if (rank < BETA) {
        pts_out[(b * NPTS + rank) * 2 + 0] = rand_over[(b * KN + t) * 2 + 0];
        pts_out[(b * NPTS + rank) * 2 + 1] = rand_over[(b * KN + t) * 2 + 1];
    }
    if (t < NCOV) {
        pts_out[(b * NPTS + BETA + t) * 2 + 0] = rand_cov[(b * NCOV + t) * 2 + 0];
        pts_out[(b * NPTS + BETA + t) * 2 + 1] = rand_cov[(b * NCOV + t) * 2 + 1];
    }
}

// ---------------------------------------------------------------------------
// Kernel 3: sample coarse (out, 128ch) + fine (res2, 64ch) features at the
// selected points. Warp per point; lane covers strided channels.
// ---------------------------------------------------------------------------
__global__ void sample_kernel(const float* __restrict__ outm,
                              const float* __restrict__ res2,
                              const float* __restrict__ pts) {
    int gw   = (blockIdx.x * blockDim.x + threadIdx.x) >> 5;
    int lane = threadIdx.x & 31;
    if (gw >= BB * NPTS) return;
    int b = gw / NPTS, n = gw % NPTS;

    float px = pts[(b * NPTS + n) * 2 + 0];
    float py = pts[(b * NPTS + n) * 2 + 1];

    // coarse: out [B,128,256,256]
    {
        float gx = px * (float)HW_OUT - 0.5f;
        float gy = py * (float)HW_OUT - 0.5f;
        float x0f = floorf(gx), y0f = floorf(gy);
        float wx = gx - x0f, wy = gy - y0f;
        int x0 = (int)x0f, y0 = (int)y0f;
        const float* base = outm + (size_t)b * C_OUT * HW_OUT * HW_OUT;
        float acc[4] = {0.f, 0.f, 0.f, 0.f};
        #pragma unroll
        for (int cy = 0; cy < 2; cy++) {
            #pragma unroll
            for (int cx = 0; cx < 2; cx++) {
                int yi = y0 + cy, xi = x0 + cx;
                if (xi < 0 || xi >= HW_OUT || yi < 0 || yi >= HW_OUT) continue;
                float wgt = (cx ? wx : 1.0f - wx) * (cy ? wy : 1.0f - wy);
                const float* pix = base + (size_t)yi * HW_OUT + xi;
                #pragma unroll
                for (int i = 0; i < 4; i++)
                    acc[i] += wgt * __ldg(pix + (size_t)(lane + 32 * i) * (HW_OUT * HW_OUT));
            }
        }
        #pragma unroll
        for (int i = 0; i < 4; i++)
            g_feat[((size_t)b * C_FEAT + (lane + 32 * i)) * NPTS + n] = acc[i];
    }
    // fine: res2 [B,64,512,512]
    {
        float gx = px * (float)HW_RES - 0.5f;
        float gy = py * (float)HW_RES - 0.5f;
        float x0f = floorf(gx), y0f = floorf(gy);
        float wx = gx - x0f, wy = gy - y0f;
        int x0 = (int)x0f, y0 = (int)y0f;
        const float* base = res2 + (size_t)b * C_RES * HW_RES * HW_RES;
        float acc[2] = {0.f, 0.f};
        #pragma unroll
        for (int cy = 0; cy < 2; cy++) {
            #pragma unroll
            for (int cx = 0; cx < 2; cx++) {
                int yi = y0 + cy, xi = x0 + cx;
                if (xi < 0 || xi >= HW_RES || yi < 0 || yi >= HW_RES) continue;
                float wgt = (cx ? wx : 1.0f - wx) * (cy ? wy : 1.0f - wy);
                const float* pix = base + (size_t)yi * HW_RES + xi;
                #pragma unroll
                for (int i = 0; i < 2; i++)
                    acc[i] += wgt * __ldg(pix + (size_t)(lane + 32 * i) * (HW_RES * HW_RES));
            }
        }
        #pragma unroll
        for (int i = 0; i < 2; i++)
            g_feat[((size_t)b * C_FEAT + C_OUT + (lane + 32 * i)) * NPTS + n] = acc[i];
    }
}

// ---------------------------------------------------------------------------
// Kernel 4: rend[b,o,n] = sum_k weight[o,k] * feat[b,k,n] + bias[o]
// Block: 128 o x 32 n tile per batch; 4x4 register blocking, smem-tiled.
// ---------------------------------------------------------------------------
__global__ void gemm_kernel(const float* __restrict__ weight,
                            const float* __restrict__ bias,
                            float* __restrict__ rend) {
    extern __shared__ float sm[];
    float* wT = sm;                   // [192][128] transposed weight
    float* fs = sm + C_FEAT * C_OUT;  // [192][32] feat tile

    int b  = blockIdx.y;
    int n0 = blockIdx.x * 32;
    int tx = threadIdx.x;             // 0..31 -> o quad
    int ty = threadIdx.y;             // 0..7  -> n quad
    int t  = ty * 32 + tx;

    for (int idx = t; idx < C_OUT * C_FEAT; idx += 256) {
        int o = idx / C_FEAT, k = idx % C_FEAT;
        wT[k * C_OUT + o] = weight[idx];
    }
    for (int idx = t; idx < C_FEAT * 32; idx += 256) {
        int k = idx / 32, j = idx % 32;
        fs[idx] = g_feat[((size_t)b * C_FEAT + k) * NPTS + n0 + j];
    }
    __syncthreads();

    float acc[4][4] = {};
    #pragma unroll 4
    for (int k = 0; k < C_FEAT; k++) {
        float4 w4 = *(const float4*)&wT[k * C_OUT + tx * 4];
        float4 f4 = *(const float4*)&fs[k * 32 + ty * 4];
        acc[0][0] += w4.x * f4.x; acc[0][1] += w4.x * f4.y; acc[0][2] += w4.x * f4.z; acc[0][3] += w4.x * f4.w;
        acc[1][0] += w4.y * f4.x; acc[1][1] += w4.y * f4.y; acc[1][2] += w4.y * f4.z; acc[1][3] += w4.y * f4.w;
        acc[2][0] += w4.z * f4.x; acc[2][1] += w4.z * f4.y; acc[2][2] += w4.z * f4.z; acc[2][3] += w4.z * f4.w;
        acc[3][0] += w4.w * f4.x; acc[3][1] += w4.w * f4.y; acc[3][2] += w4.w * f4.z; acc[3][3] += w4.w * f4.w;
    }
    #pragma unroll
    for (int i = 0; i < 4; i++) {
        int o = tx * 4 + i;
        float bv = bias[o];
        #pragma unroll
        for (int j = 0; j < 4; j++) {
            rend[((size_t)b * C_OUT + o) * NPTS + n0 + ty * 4 + j] = acc[i][j] + bv;
        }
    }
}

// ---------------------------------------------------------------------------
extern "C" void kernel_launch(void* const* d_in, const int* in_sizes, int n_in,
                              void* d_out, int out_size) {
    // metadata order: x, res2, out, rand_over, rand_cov, weight, bias
    const float* res2      = (const float*)d_in[1];
    const float* outm      = (const float*)d_in[2];
    const float* rand_over = (const float*)d_in[3];
    const float* rand_cov  = (const float*)d_in[4];
    const float* weight    = (const float*)d_in[5];
    const float* bias      = (const float*)d_in[6];

    float* rend = (float*)d_out;                 // [8,128,256]
    float* pts  = (float*)d_out + REND_ELEMS;    // [8,256,2]

    static const int gemm_smem = (C_FEAT * C_OUT + C_FEAT * 32) * (int)sizeof(float); // 122880
    cudaFuncSetAttribute(gemm_kernel, cudaFuncAttributeMaxDynamicSharedMemorySize, gemm_smem);

    // 1) uncertainty: warp per point, 8 warps per block
    unc_kernel<<<(BB * KN) / 8, 256>>>(outm, rand_over);
    // 2) exact top-k + assemble points into d_out tail
    topk_kernel<<<BB, KN>>>(rand_over, rand_cov, pts);
    // 3) feature sampling at selected points
    sample_kernel<<<(BB * NPTS) / 8, 256>>>(outm, res2, pts);
    // 4) 1x1 conv GEMM + bias
    dim3 ggrid(NPTS / 32, BB);
    dim3 gblk(32, 8);
    gemm_kernel<<<ggrid, gblk, gemm_smem>>>(weight, bias, rend);
}

// round 8
// speedup vs baseline: 1.0391x; 1.0391x over previous
#include <cuda_runtime.h>
#include <math.h>

// Problem constants (fixed shapes from setup_inputs)
#define BB      8
#define KN      768      // K*N = 3*256
#define NPTS    256      // N
#define BETA    192      // int(0.75*N)
#define NCOV    64       // N - BETA
#define C_OUT   128
#define HW_OUT  256
#define C_RES   64
#define HW_RES  512
#define C_FEAT  192
#define REND_ELEMS (BB*C_OUT*NPTS)   // 262144

// Scratch (no allocations allowed)
__device__ float g_unc[BB * KN];
__device__ float g_feat[(size_t)BB * C_FEAT * NPTS];

// ---------------------------------------------------------------------------
// Kernel 1: uncertainty per rand_over point.
// Warp per point: top-2 over 128 channels at each of 4 bilinear corners,
// then bilinear combine exactly mirroring the reference arithmetic order.
// ---------------------------------------------------------------------------
__global__ void unc_kernel(const float* __restrict__ outm,
                           const float* __restrict__ rand_over) {
    int gw   = (blockIdx.x * blockDim.x + threadIdx.x) >> 5;
    int lane = threadIdx.x & 31;
    if (gw >= BB * KN) return;
    int b = gw / KN, p = gw % KN;

    float px = rand_over[(b * KN + p) * 2 + 0];
    float py = rand_over[(b * KN + p) * 2 + 1];
    float gx = px * (float)HW_OUT - 0.5f;
    float gy = py * (float)HW_OUT - 0.5f;
    float x0f = floorf(gx), y0f = floorf(gy);
    float wx = gx - x0f, wy = gy - y0f;
    int x0 = (int)x0f, y0 = (int)y0f;

    const float* base = outm + (size_t)b * C_OUT * HW_OUT * HW_OUT;
    float og0 = 0.0f, og1 = 0.0f;

    #pragma unroll
    for (int cy = 0; cy < 2; cy++) {
        #pragma unroll
        for (int cx = 0; cx < 2; cx++) {
            int yi = y0 + cy, xi = x0 + cx;
            float t1, t2;
            if (xi >= 0 && xi < HW_OUT && yi >= 0 && yi < HW_OUT) {
                t1 = -INFINITY; t2 = -INFINITY;
                const float* pix = base + (size_t)yi * HW_OUT + xi;
                #pragma unroll
                for (int i = 0; i < 4; i++) {
                    float v = __ldg(pix + (size_t)(lane + 32 * i) * (HW_OUT * HW_OUT));
                    if (v > t1) { t2 = t1; t1 = v; }
                    else if (v > t2) { t2 = v; }
                }
                #pragma unroll
                for (int off = 16; off; off >>= 1) {
                    float o1 = __shfl_xor_sync(0xffffffffu, t1, off);
                    float o2 = __shfl_xor_sync(0xffffffffu, t2, off);
                    float n1 = fmaxf(t1, o1);
                    float n2 = fmaxf(fminf(t1, o1), fmaxf(t2, o2));
                    t1 = n1; t2 = n2;
                }
            } else {
                t1 = 0.0f; t2 = 0.0f;   // zero padding
            }
            float fx = cx ? wx : (1.0f - wx);
            float fy = cy ? wy : (1.0f - wy);
            // mirror reference: v * fx * fy, summed in corner order 00,01,10,11
            og0 += (t1 * fx) * fy;
            og1 += (t2 * fx) * fy;
        }
    }
    if (lane == 0) g_unc[b * KN + p] = og1 - og0;   // -(og0 - og1)
}

// ---------------------------------------------------------------------------
// Kernel 2: exact top-BETA selection per batch (matches lax.top_k ordering:
// descending value, ties broken by lower index). Rank-by-comparison O(N^2).
// Writes points (importance then rand_cov) into d_out tail region.
// ---------------------------------------------------------------------------
__global__ void topk_kernel(const float* __restrict__ rand_over,
                            const float* __restrict__ rand_cov,
                            float* __restrict__ pts_out) {
    __shared__ float su[KN];
    int b = blockIdx.x;
    int t = threadIdx.x;       // blockDim.x == KN
    su[t] = g_unc[b * KN + t];
    __syncthreads();
    float v = su[t];
    int rank = 0;
    for (int j = 0; j < KN; j++) {
        float vj = su[j];
        rank += (vj > v) || (vj == v && j < t);
    }
    if (rank < BETA) {
        pts_out[(b * NPTS + rank) * 2 + 0] = rand_over[(b * KN + t) * 2 + 0];
        pts_out[(b * NPTS + rank) * 2 + 1] = rand_over[(b * KN + t) * 2 + 1];
    }
    if (t < NCOV) {
        pts_out[(b * NPTS + BETA + t) * 2 + 0] = rand_cov[(b * NCOV + t) * 2 + 0];
        pts_out[(b * NPTS + BETA + t) * 2 + 1] = rand_cov[(b * NCOV + t) * 2 + 1];
    }
}

// ---------------------------------------------------------------------------
// Kernel 3: sample coarse (out, 128ch) + fine (res2, 64ch) features at the
// selected points. Warp per point; lane covers strided channels.
// ---------------------------------------------------------------------------
__global__ void sample_kernel(const float* __restrict__ outm,
                              const float* __restrict__ res2,
                              const float* __restrict__ pts) {
    int gw   = (blockIdx.x * blockDim.x + threadIdx.x) >> 5;
    int lane = threadIdx.x & 31;
    if (gw >= BB * NPTS) return;
    int b = gw / NPTS, n = gw % NPTS;

    float px = pts[(b * NPTS + n) * 2 + 0];
    float py = pts[(b * NPTS + n) * 2 + 1];

    // coarse: out [B,128,256,256]
    {
        float gx = px * (float)HW_OUT - 0.5f;
        float gy = py * (float)HW_OUT - 0.5f;
        float x0f = floorf(gx), y0f = floorf(gy);
        float wx = gx - x0f, wy = gy - y0f;
        int x0 = (int)x0f, y0 = (int)y0f;
        const float* base = outm + (size_t)b * C_OUT * HW_OUT * HW_OUT;
        float acc[4] = {0.f, 0.f, 0.f, 0.f};
        #pragma unroll
        for (int cy = 0; cy < 2; cy++) {
            #pragma unroll
            for (int cx = 0; cx < 2; cx++) {
                int yi = y0 + cy, xi = x0 + cx;
                if (xi < 0 || xi >= HW_OUT || yi < 0 || yi >= HW_OUT) continue;
                float wgt = (cx ? wx : 1.0f - wx) * (cy ? wy : 1.0f - wy);
                const float* pix = base + (size_t)yi * HW_OUT + xi;
                #pragma unroll
                for (int i = 0; i < 4; i++)
                    acc[i] += wgt * __ldg(pix + (size_t)(lane + 32 * i) * (HW_OUT * HW_OUT));
            }
        }
        #pragma unroll
        for (int i = 0; i < 4; i++)
            g_feat[((size_t)b * C_FEAT + (lane + 32 * i)) * NPTS + n] = acc[i];
    }
    // fine: res2 [B,64,512,512]
    {
        float gx = px * (float)HW_RES - 0.5f;
        float gy = py * (float)HW_RES - 0.5f;
        float x0f = floorf(gx), y0f = floorf(gy);
        float wx = gx - x0f, wy = gy - y0f;
        int x0 = (int)x0f, y0 = (int)y0f;
        const float* base = res2 + (size_t)b * C_RES * HW_RES * HW_RES;
        float acc[2] = {0.f, 0.f};
        #pragma unroll
        for (int cy = 0; cy < 2; cy++) {
            #pragma unroll
            for (int cx = 0; cx < 2; cx++) {
                int yi = y0 + cy, xi = x0 + cx;
                if (xi < 0 || xi >= HW_RES || yi < 0 || yi >= HW_RES) continue;
                float wgt = (cx ? wx : 1.0f - wx) * (cy ? wy : 1.0f - wy);
                const float* pix = base + (size_t)yi * HW_RES + xi;
                #pragma unroll
                for (int i = 0; i < 2; i++)
                    acc[i] += wgt * __ldg(pix + (size_t)(lane + 32 * i) * (HW_RES * HW_RES));
            }
        }
        #pragma unroll
        for (int i = 0; i < 2; i++)
            g_feat[((size_t)b * C_FEAT + C_OUT + (lane + 32 * i)) * NPTS + n] = acc[i];
    }
}

// ---------------------------------------------------------------------------
// Kernel 4: rend[b,o,n] = sum_k weight[o,k] * feat[b,k,n] + bias[o]
// Block: 128 o x 32 n tile per batch; 4x4 register blocking, smem-tiled.
// ---------------------------------------------------------------------------
__global__ void gemm_kernel(const float* __restrict__ weight,
                            const float* __restrict__ bias,
                            float* __restrict__ rend) {
    extern __shared__ float sm[];
    float* wT = sm;                   // [192][128] transposed weight
    float* fs = sm + C_FEAT * C_OUT;  // [192][32] feat tile

    int b  = blockIdx.y;
    int n0 = blockIdx.x * 32;
    int tx = threadIdx.x;             // 0..31 -> o quad
    int ty = threadIdx.y;             // 0..7  -> n quad
    int t  = ty * 32 + tx;

    for (int idx = t; idx < C_OUT * C_FEAT; idx += 256) {
        int o = idx / C_FEAT, k = idx % C_FEAT;
        wT[k * C_OUT + o] = weight[idx];
    }
    for (int idx = t; idx < C_FEAT * 32; idx += 256) {
        int k = idx / 32, j = idx % 32;
        fs[idx] = g_feat[((size_t)b * C_FEAT + k) * NPTS + n0 + j];
    }
    __syncthreads();

    float acc[4][4] = {};
    #pragma unroll 4
    for (int k = 0; k < C_FEAT; k++) {
        float4 w4 = *(const float4*)&wT[k * C_OUT + tx * 4];
        float4 f4 = *(const float4*)&fs[k * 32 + ty * 4];
        acc[0][0] += w4.x * f4.x; acc[0][1] += w4.x * f4.y; acc[0][2] += w4.x * f4.z; acc[0][3] += w4.x * f4.w;
        acc[1][0] += w4.y * f4.x; acc[1][1] += w4.y * f4.y; acc[1][2] += w4.y * f4.z; acc[1][3] += w4.y * f4.w;
        acc[2][0] += w4.z * f4.x; acc[2][1] += w4.z * f4.y; acc[2][2] += w4.z * f4.z; acc[2][3] += w4.z * f4.w;
        acc[3][0] += w4.w * f4.x; acc[3][1] += w4.w * f4.y; acc[3][2] += w4.w * f4.z; acc[3][3] += w4.w * f4.w;
    }
    #pragma unroll
    for (int i = 0; i < 4; i++) {
        int o = tx * 4 + i;
        float bv = bias[o];
        #pragma unroll
        for (int j = 0; j < 4; j++) {
            rend[((size_t)b * C_OUT + o) * NPTS + n0 + ty * 4 + j] = acc[i][j] + bv;
        }
    }
}

// ---------------------------------------------------------------------------
extern "C" void kernel_launch(void* const* d_in, const int* in_sizes, int n_in,
                              void* d_out, int out_size) {
    // metadata order: x, res2, out, rand_over, rand_cov, weight, bias
    const float* res2      = (const float*)d_in[1];
    const float* outm      = (const float*)d_in[2];
    const float* rand_over = (const float*)d_in[3];
    const float* rand_cov  = (const float*)d_in[4];
    const float* weight    = (const float*)d_in[5];
    const float* bias      = (const float*)d_in[6];

    float* rend = (float*)d_out;                 // [8,128,256]
    float* pts  = (float*)d_out + REND_ELEMS;    // [8,256,2]

    static const int gemm_smem = (C_FEAT * C_OUT + C_FEAT * 32) * (int)sizeof(float); // 122880
    cudaFuncSetAttribute(gemm_kernel, cudaFuncAttributeMaxDynamicSharedMemorySize, gemm_smem);

    // 1) uncertainty: warp per point, 8 warps per block
    unc_kernel<<<(BB * KN) / 8, 256>>>(outm, rand_over);
    // 2) exact top-k + assemble points into d_out tail
    topk_kernel<<<BB, KN>>>(rand_over, rand_cov, pts);
    // 3) feature sampling at selected points
    sample_kernel<<<(BB * NPTS) / 8, 256>>>(outm, res2, pts);
    // 4) 1x1 conv GEMM + bias
    dim3 ggrid(NPTS / 32, BB);
    dim3 gblk(32, 8);
    gemm_kernel<<<ggrid, gblk, gemm_smem>>>(weight, bias, rend);
}

// round 10
// speedup vs baseline: 1.1225x; 1.0803x over previous
#include <cuda_runtime.h>
#include <math.h>

// Problem constants (fixed shapes from setup_inputs)
#define BB      8
#define KN      768      // K*N = 3*256
#define NPTS    256      // N
#define BETA    192      // int(0.75*N)
#define NCOV    64       // N - BETA
#define C_OUT   128
#define HW_OUT  256
#define C_RES   64
#define HW_RES  512
#define C_FEAT  192
#define REND_ELEMS (BB*C_OUT*NPTS)   // 262144

// Scratch (no allocations allowed)
__device__ float g_unc[BB * KN];
__device__ float g_feat[(size_t)BB * C_FEAT * NPTS];

// ---------------------------------------------------------------------------
// Kernel 1: uncertainty per rand_over point. Warp per point.
// Branch-free: clamp indices, issue all 16 loads up front (MLP=16/lane),
// fmax-based top2-of-4, validity applied post-reduction. Value-exact vs
// the previous passing version (same shuffle-reduce and combine order).
// ---------------------------------------------------------------------------
__global__ void unc_kernel(const float* __restrict__ outm,
                           const float* __restrict__ rand_over) {
    int gw   = (blockIdx.x * blockDim.x + threadIdx.x) >> 5;
    int lane = threadIdx.x & 31;
    if (gw >= BB * KN) return;
    int b = gw / KN, p = gw % KN;

    float px = rand_over[(b * KN + p) * 2 + 0];
    float py = rand_over[(b * KN + p) * 2 + 1];
    float gx = px * (float)HW_OUT - 0.5f;
    float gy = py * (float)HW_OUT - 0.5f;
    float x0f = floorf(gx), y0f = floorf(gy);
    float wx = gx - x0f, wy = gy - y0f;
    int x0 = (int)x0f, y0 = (int)y0f;
    int x1 = x0 + 1, y1 = y0 + 1;

    int xc0 = min(max(x0, 0), HW_OUT - 1), xc1 = min(max(x1, 0), HW_OUT - 1);
    int yc0 = min(max(y0, 0), HW_OUT - 1), yc1 = min(max(y1, 0), HW_OUT - 1);
    bool vx0 = (x0 >= 0) & (x0 < HW_OUT), vx1 = (x1 >= 0) & (x1 < HW_OUT);
    bool vy0 = (y0 >= 0) & (y0 < HW_OUT), vy1 = (y1 >= 0) & (y1 < HW_OUT);

    const float* pl = outm + (size_t)b * C_OUT * HW_OUT * HW_OUT
                           + (size_t)lane * (HW_OUT * HW_OUT);
    int o00 = yc0 * HW_OUT + xc0, o01 = yc0 * HW_OUT + xc1;
    int o10 = yc1 * HW_OUT + xc0, o11 = yc1 * HW_OUT + xc1;

    float v[4][4];   // [corner][channel group]
    #pragma unroll
    for (int i = 0; i < 4; i++) {
        const float* q = pl + (size_t)i * 32 * (HW_OUT * HW_OUT);
        v[0][i] = __ldg(q + o00);
        v[1][i] = __ldg(q + o01);
        v[2][i] = __ldg(q + o10);
        v[3][i] = __ldg(q + o11);
    }

    float t1[4], t2[4];
    #pragma unroll
    for (int c = 0; c < 4; c++) {
        float m01 = fmaxf(v[c][0], v[c][1]), n01 = fminf(v[c][0], v[c][1]);
        float m23 = fmaxf(v[c][2], v[c][3]), n23 = fminf(v[c][2], v[c][3]);
        t1[c] = fmaxf(m01, m23);
        t2[c] = fmaxf(fminf(m01, m23), fmaxf(n01, n23));
    }
    #pragma unroll
    for (int off = 16; off; off >>= 1) {
        #pragma unroll
        for (int c = 0; c < 4; c++) {
            float o1 = __shfl_xor_sync(0xffffffffu, t1[c], off);
            float o2 = __shfl_xor_sync(0xffffffffu, t2[c], off);
            float n1 = fmaxf(t1[c], o1);
            float n2 = fmaxf(fminf(t1[c], o1), fmaxf(t2[c], o2));
            t1[c] = n1; t2[c] = n2;
        }
    }
    bool val[4] = { vy0 && vx0, vy0 && vx1, vy1 && vx0, vy1 && vx1 };
    float fxs[4] = { 1.0f - wx, wx, 1.0f - wx, wx };
    float fys[4] = { 1.0f - wy, 1.0f - wy, wy, wy };
    float og0 = 0.0f, og1 = 0.0f;
    #pragma unroll
    for (int c = 0; c < 4; c++) {
        float a = val[c] ? t1[c] : 0.0f;
        float s = val[c] ? t2[c] : 0.0f;
        og0 += (a * fxs[c]) * fys[c];
        og1 += (s * fxs[c]) * fys[c];
    }
    if (lane == 0) g_unc[b * KN + p] = og1 - og0;   // -(og0 - og1)
}

// ---------------------------------------------------------------------------
// Kernel 2: exact top-BETA selection per batch (lax.top_k ordering:
// descending value, ties -> lower index). Rank-by-comparison O(N^2).
// ---------------------------------------------------------------------------
__global__ void topk_kernel(const float* __restrict__ rand_over,
                            const float* __restrict__ rand_cov,
                            float* __restrict__ pts_out) {
    __shared__ float su[KN];
    int b = blockIdx.x;
    int t = threadIdx.x;       // blockDim.x == KN
    su[t] = g_unc[b * KN + t];
    __syncthreads();
    float v = su[t];
    int rank = 0;
    #pragma unroll 8
    for (int j = 0; j < KN; j++) {
        float vj = su[j];
        rank += (vj > v) || (vj == v && j < t);
    }
    if (rank < BETA) {
        pts_out[(b * NPTS + rank) * 2 + 0] = rand_over[(b * KN + t) * 2 + 0];
        pts_out[(b * NPTS + rank) * 2 + 1] = rand_over[(b * KN + t) * 2 + 1];
    }
    if (t < NCOV) {
        pts_out[(b * NPTS + BETA + t) * 2 + 0] = rand_cov[(b * NCOV + t) * 2 + 0];
        pts_out[(b * NPTS + BETA + t) * 2 + 1] = rand_cov[(b * NCOV + t) * 2 + 1];
    }
}

// ---------------------------------------------------------------------------
// Kernel 3: sample coarse (out, 128ch) + fine (res2, 64ch) at selected
// points. Warp per point; all 24 corner loads issued up front (MLP=24).
// ---------------------------------------------------------------------------
__global__ void sample_kernel(const float* __restrict__ outm,
                              const float* __restrict__ res2,
                              const float* __restrict__ pts) {
    int gw   = (blockIdx.x * blockDim.x + threadIdx.x) >> 5;
    int lane = threadIdx.x & 31;
    if (gw >= BB * NPTS) return;
    int b = gw / NPTS, n = gw % NPTS;

    float px = pts[(b * NPTS + n) * 2 + 0];
    float py = pts[(b * NPTS + n) * 2 + 1];

    // ---- coarse: out [B,128,256,256] ----
    {
        float gx = px * (float)HW_OUT - 0.5f;
        float gy = py * (float)HW_OUT - 0.5f;
        float x0f = floorf(gx), y0f = floorf(gy);
        float wx = gx - x0f, wy = gy - y0f;
        int x0 = (int)x0f, y0 = (int)y0f, x1 = x0 + 1, y1 = y0 + 1;
        int xc0 = min(max(x0, 0), HW_OUT - 1), xc1 = min(max(x1, 0), HW_OUT - 1);
        int yc0 = min(max(y0, 0), HW_OUT - 1), yc1 = min(max(y1, 0), HW_OUT - 1);
        float vx0 = (x0 >= 0 && x0 < HW_OUT) ? 1.f : 0.f;
        float vx1 = (x1 >= 0 && x1 < HW_OUT) ? 1.f : 0.f;
        float vy0 = (y0 >= 0 && y0 < HW_OUT) ? 1.f : 0.f;
        float vy1 = (y1 >= 0 && y1 < HW_OUT) ? 1.f : 0.f;
        float w00 = (1.f - wx) * (1.f - wy) * vx0 * vy0;
        float w01 = wx * (1.f - wy) * vx1 * vy0;
        float w10 = (1.f - wx) * wy * vx0 * vy1;
        float w11 = wx * wy * vx1 * vy1;
        int o00 = yc0 * HW_OUT + xc0, o01 = yc0 * HW_OUT + xc1;
        int o10 = yc1 * HW_OUT + xc0, o11 = yc1 * HW_OUT + xc1;
        const float* pl = outm + (size_t)b * C_OUT * HW_OUT * HW_OUT
                               + (size_t)lane * (HW_OUT * HW_OUT);
        float c00[4], c01[4], c10[4], c11[4];
        #pragma unroll
        for (int i = 0; i < 4; i++) {
            const float* q = pl + (size_t)i * 32 * (HW_OUT * HW_OUT);
            c00[i] = __ldg(q + o00); c01[i] = __ldg(q + o01);
            c10[i] = __ldg(q + o10); c11[i] = __ldg(q + o11);
        }
        #pragma unroll
        for (int i = 0; i < 4; i++) {
            float acc = w00 * c00[i] + w01 * c01[i] + w10 * c10[i] + w11 * c11[i];
            g_feat[((size_t)b * C_FEAT + (lane + 32 * i)) * NPTS + n] = acc;
        }
    }
    // ---- fine: res2 [B,64,512,512] ----
    {
        float gx = px * (float)HW_RES - 0.5f;
        float gy = py * (float)HW_RES - 0.5f;
        float x0f = floorf(gx), y0f = floorf(gy);
        float wx = gx - x0f, wy = gy - y0f;
        int x0 = (int)x0f, y0 = (int)y0f, x1 = x0 + 1, y1 = y0 + 1;
        int xc0 = min(max(x0, 0), HW_RES - 1), xc1 = min(max(x1, 0), HW_RES - 1);
        int yc0 = min(max(y0, 0), HW_RES - 1), yc1 = min(max(y1, 0), HW_RES - 1);
        float vx0 = (x0 >= 0 && x0 < HW_RES) ? 1.f : 0.f;
        float vx1 = (x1 >= 0 && x1 < HW_RES) ? 1.f : 0.f;
        float vy0 = (y0 >= 0 && y0 < HW_RES) ? 1.f : 0.f;
        float vy1 = (y1 >= 0 && y1 < HW_RES) ? 1.f : 0.f;
        float w00 = (1.f - wx) * (1.f - wy) * vx0 * vy0;
        float w01 = wx * (1.f - wy) * vx1 * vy0;
        float w10 = (1.f - wx) * wy * vx0 * vy1;
        float w11 = wx * wy * vx1 * vy1;
        int o00 = yc0 * HW_RES + xc0, o01 = yc0 * HW_RES + xc1;
        int o10 = yc1 * HW_RES + xc0, o11 = yc1 * HW_RES + xc1;
        const float* pl = res2 + (size_t)b * C_RES * HW_RES * HW_RES
                               + (size_t)lane * (HW_RES * HW_RES);
        float c00[2], c01[2], c10[2], c11[2];
        #pragma unroll
        for (int i = 0; i < 2; i++) {
            const float* q = pl + (size_t)i * 32 * (HW_RES * HW_RES);
            c00[i] = __ldg(q + o00); c01[i] = __ldg(q + o01);
            c10[i] = __ldg(q + o10); c11[i] = __ldg(q + o11);
        }
        #pragma unroll
        for (int i = 0; i < 2; i++) {
            float acc = w00 * c00[i] + w01 * c01[i] + w10 * c10[i] + w11 * c11[i];
            g_feat[((size_t)b * C_FEAT + C_OUT + (lane + 32 * i)) * NPTS + n] = acc;
        }
    }
}

// ---------------------------------------------------------------------------
// Kernel 4 (rewritten): rend[b,o,n] = sum_k W[o,k]*feat[b,k,n] + bias[o]
// 64(o) x 32(n) tile per block, 128 threads, 4x4 register blocking.
// wT padded to 68 floats/row for 16B-aligned float4 reads, conflict-free.
// grid = 8 n-tiles x 2 o-tiles x 8 batches = 128 blocks (1 wave).
// ---------------------------------------------------------------------------
#define GT_O 64
#define GT_N 32
#define WPAD 68   // 64 + 4 pad; multiple of 4 for float4 alignment
__global__ void gemm_kernel(const float* __restrict__ weight,
                            const float* __restrict__ bias,
                            float* __restrict__ rend) {
    extern __shared__ float sm[];
    float* wT = sm;                     // [192][WPAD]
    float* fs = sm + C_FEAT * WPAD;     // [192][32]

    int b  = blockIdx.z;
    int o0 = blockIdx.y * GT_O;
    int n0 = blockIdx.x * GT_N;
    int t  = threadIdx.x;               // 128 threads

    // Load weight tile transposed: consecutive threads -> consecutive k
    // (coalesced global), smem stride WPAD=68 (bank-friendly).
    for (int idx = t; idx < GT_O * C_FEAT; idx += 128) {
        int o = idx / C_FEAT, k = idx % C_FEAT;
        wT[k * WPAD + o] = weight[(o0 + o) * C_FEAT + k];
    }
    // Load feat tile: contiguous in n (coalesced).
    for (int idx = t; idx < C_FEAT * GT_N; idx += 128) {
        int k = idx / GT_N, j = idx % GT_N;
        fs[idx] = g_feat[((size_t)b * C_FEAT + k) * NPTS + n0 + j];
    }
    __syncthreads();

    int tx = t & 7;     // n quad: n = n0 + tx*4
    int ty = t >> 3;    // o quad: o = o0 + ty*4 (0..15)

    float acc[4][4] = {};
    #pragma unroll 4
    for (int k = 0; k < C_FEAT; k++) {
        float4 w4 = *(const float4*)&wT[k * WPAD + ty * 4];
        float4 f4 = *(const float4*)&fs[k * GT_N + tx * 4];
        acc[0][0] += w4.x * f4.x; acc[0][1] += w4.x * f4.y; acc[0][2] += w4.x * f4.z; acc[0][3] += w4.x * f4.w;
        acc[1][0] += w4.y * f4.x; acc[1][1] += w4.y * f4.y; acc[1][2] += w4.y * f4.z; acc[1][3] += w4.y * f4.w;
        acc[2][0] += w4.z * f4.x; acc[2][1] += w4.z * f4.y; acc[2][2] += w4.z * f4.z; acc[2][3] += w4.z * f4.w;
        acc[3][0] += w4.w * f4.x; acc[3][1] += w4.w * f4.y; acc[3][2] += w4.w * f4.z; acc[3][3] += w4.w * f4.w;
    }
    #pragma unroll
    for (int i = 0; i < 4; i++) {
        int o = o0 + ty * 4 + i;
        float bv = bias[o];
        float4 r = make_float4(acc[i][0] + bv, acc[i][1] + bv,
                               acc[i][2] + bv, acc[i][3] + bv);
        *(float4*)&rend[((size_t)b * C_OUT + o) * NPTS + n0 + tx * 4] = r;
    }
}

// ---------------------------------------------------------------------------
extern "C" void kernel_launch(void* const* d_in, const int* in_sizes, int n_in,
                              void* d_out, int out_size) {
    // metadata order: x, res2, out, rand_over, rand_cov, weight, bias
    const float* res2      = (const float*)d_in[1];
    const float* outm      = (const float*)d_in[2];
    const float* rand_over = (const float*)d_in[3];
    const float* rand_cov  = (const float*)d_in[4];
    const float* weight    = (const float*)d_in[5];
    const float* bias      = (const float*)d_in[6];

    float* rend = (float*)d_out;                 // [8,128,256]
    float* pts  = (float*)d_out + REND_ELEMS;    // [8,256,2]

    static const int gemm_smem = (C_FEAT * WPAD + C_FEAT * GT_N) * (int)sizeof(float); // 76800
    cudaFuncSetAttribute(gemm_kernel, cudaFuncAttributeMaxDynamicSharedMemorySize, gemm_smem);

    // 1) uncertainty: warp per point, 8 warps per block
    unc_kernel<<<(BB * KN) / 8, 256>>>(outm, rand_over);
    // 2) exact top-k + assemble points into d_out tail
    topk_kernel<<<BB, KN>>>(rand_over, rand_cov, pts);
    // 3) feature sampling at selected points
    sample_kernel<<<(BB * NPTS) / 8, 256>>>(outm, res2, pts);
    // 4) 1x1 conv GEMM + bias: 128 blocks x 128 threads
    dim3 ggrid(NPTS / GT_N, C_OUT / GT_O, BB);
    gemm_kernel<<<ggrid, 128, gemm_smem>>>(weight, bias, rend);
}